// round 14
// baseline (speedup 1.0000x reference)
#include <cuda_runtime.h>

#define NB   2
#define CIN  16
#define CM   24
#define HIN  384
#define WIN  1280
#define HO   96
#define WL   320
#define WR   1280
#define DMAX 64

// scratch (device globals: no allocation allowed)
__device__ float g_fl[(size_t)NB*CM*HO*WL];
__device__ float g_fr[(size_t)NB*CM*HO*WR];

typedef unsigned long long ull;

__device__ __forceinline__ ull pack2(float lo, float hi) {
    ull r; asm("mov.b64 %0,{%1,%2};" : "=l"(r) : "f"(lo), "f"(hi)); return r;
}
__device__ __forceinline__ void unpack2(ull v, float& lo, float& hi) {
    asm("mov.b64 {%0,%1},%2;" : "=f"(lo), "=f"(hi) : "l"(v));
}
__device__ __forceinline__ ull fma2(ull a, ull b, ull c) {
    ull d; asm("fma.rn.f32x2 %0,%1,%2,%3;" : "=l"(d) : "l"(a), "l"(b), "l"(c)); return d;
}
__device__ __forceinline__ ull add2(ull a, ull b) {
    ull d; asm("add.rn.f32x2 %0,%1,%2;" : "=l"(d) : "l"(a), "l"(b)); return d;
}
__device__ __forceinline__ ull neg2(ull a) { return a ^ 0x8000000080000000ULL; }
__device__ __forceinline__ ull lrelu2(ull v) {
    float lo, hi; unpack2(v, lo, hi);
    lo = lo > 0.f ? lo : 0.2f * lo;
    hi = hi > 0.f ? hi : 0.2f * hi;
    return pack2(lo, hi);
}

// conv smem layout (ull units):
//   wg (Winograd F(2,4) transformed em weights, channel-pair packed, for RIGHT branch):
//     sw_wg[(ci*4+kh)*60 + j*12 + cp] = ( Wj[2cp], Wj[2cp+1] ),
//       W0=w0, W1=w0+w1+w2+w3, W2=w0-w1+w2-w3, W3=w0+2w1+4w2+8w3, W4=w3  (w indexed by kw)
//   em (direct layout for LEFT branch):
//     sw_em[(((ci*4+kh)*4)+kw)*12 + cp] = ( wem[2cp][ci][kh][kw], wem[2cp+1][ci][kh][kw] )
//   rc: sw_rc[co*CM + c] = ( wrc[co][c], wrc[co][c] )
//   sb_em[cp] = (bem[2cp], bem[2cp+1]);  sb_rc[co] = (brc[co], brc[co])
#define SM_WG (64*60)          // 3840 ull
#define SM_EM (CIN*16*12)      // 3072 ull
#define SM_RC (CM*CM)          // 576 ull
#define SMW_ULL (SM_WG + SM_EM + SM_RC + 12 + CM)   // 7524 ull = 60192 B

#define NLEFT_BLK 240          // 2*96*160 / 128   (2 px/thread)
#define NRIGHT_BLK 960         // 2*96*640 / 128

__device__ __forceinline__ void load_weights_smem(ull* sm, const float* wem, const float* bem,
                                                  const float* wrc, const float* brc, int tid, int nthr) {
    ull* sw_wg = sm;
    ull* sw_em = sm + SM_WG;
    ull* sw_rc = sw_em + SM_EM;
    ull* sb_em = sw_rc + SM_RC;
    ull* sb_rc = sb_em + 12;
    // Winograd-transformed weights: i = (ci,kh)*12 + cp, 64*12 = 768 entries
    for (int i = tid; i < 64 * 12; i += nthr) {
        const int cp = i % 12;
        const int r2 = i / 12;           // ci*4 + kh
        const int kh = r2 & 3, ci = r2 >> 2;
        float wa[4], wb[4];
        #pragma unroll
        for (int k = 0; k < 4; k++) {
            wa[k] = wem[(((2 * cp    ) * CIN + ci) * 4 + kh) * 4 + k];
            wb[k] = wem[(((2 * cp + 1) * CIN + ci) * 4 + kh) * 4 + k];
        }
        ull* base = sw_wg + r2 * 60 + cp;
        base[0]  = pack2(wa[0], wb[0]);
        base[12] = pack2(wa[0] + wa[1] + wa[2] + wa[3], wb[0] + wb[1] + wb[2] + wb[3]);
        base[24] = pack2(wa[0] - wa[1] + wa[2] - wa[3], wb[0] - wb[1] + wb[2] - wb[3]);
        base[36] = pack2(wa[0] + 2.f*wa[1] + 4.f*wa[2] + 8.f*wa[3],
                         wb[0] + 2.f*wb[1] + 4.f*wb[2] + 8.f*wb[3]);
        base[48] = pack2(wa[3], wb[3]);
    }
    // direct em weights (left branch)
    for (int i = tid; i < SM_EM; i += nthr) {
        const int cp = i % 12;
        const int kw = (i / 12) & 3;
        const int r2 = i / 48;           // ci*4 + kh
        const int kh = r2 & 3, ci = r2 >> 2;
        const float w0 = wem[(((2 * cp    ) * CIN + ci) * 4 + kh) * 4 + kw];
        const float w1 = wem[(((2 * cp + 1) * CIN + ci) * 4 + kh) * 4 + kw];
        sw_em[i] = pack2(w0, w1);
    }
    for (int i = tid; i < SM_RC; i += nthr) { float w = wrc[i]; sw_rc[i] = pack2(w, w); }
    if (tid < 12) sb_em[tid] = pack2(bem[2 * tid], bem[2 * tid + 1]);
    if (tid < CM) { float v = brc[tid]; sb_rc[tid] = pack2(v, v); }
}

// shared epilogue: pp[...] pixel-pair packed mid features -> 1x1 rc conv -> store
__device__ __forceinline__ void rc_epilogue(const ull* sw_rc, const ull* sb_rc, const ull* pp,
                                            float* gout, int b, int hh, int t, int W)
{
    #pragma unroll 2
    for (int co = 0; co < CM; co++) {
        ull s = sb_rc[co];
        #pragma unroll
        for (int c2 = 0; c2 < CM / 2; c2++) {
            const ulonglong2 w = *(const ulonglong2*)(sw_rc + co * CM + 2 * c2);
            s = fma2(pp[2 * c2], w.x, s);
            s = fma2(pp[2 * c2 + 1], w.y, s);
        }
        s = lrelu2(s);
        float lo, hi; unpack2(s, lo, hi);
        *(float2*)(gout + (((size_t)b * CM + co) * HO + hh) * W + 2 * t) = make_float2(lo, hi);
    }
}

// ---------------- LEFT branch: direct (stride 4, no width overlap) ----------------
__device__ __forceinline__ void conv_body_left(const float* __restrict__ in, const ull* sm, int g)
{
    const ull* sw_em = sm + SM_WG;
    const ull* sw_rc = sw_em + SM_EM;
    const ull* sb_em = sw_rc + SM_RC;
    const ull* sb_rc = sb_em + 12;

    const int t  = g % 160;
    const int hh = (g / 160) % HO;
    const int b  = g / (160 * HO);

    ull acc0[12], acc1[12];
    #pragma unroll
    for (int cp = 0; cp < 12; cp++) { acc0[cp] = sb_em[cp]; acc1[cp] = sb_em[cp]; }

    const float* inb = in + (size_t)b * CIN * HIN * WIN;

    #pragma unroll 1
    for (int ci = 0; ci < CIN; ci++) {
        #pragma unroll
        for (int kh = 0; kh < 4; kh++) {
            const float* row = inb + (size_t)(ci * HIN + 4 * hh + kh) * WIN;
            const float4 v0 = *(const float4*)(row + 8 * t);
            const float4 v1 = *(const float4*)(row + 8 * t + 4);
            ull xA[4], xB[4];
            xA[0] = pack2(v0.x, v0.x); xA[1] = pack2(v0.y, v0.y);
            xA[2] = pack2(v0.z, v0.z); xA[3] = pack2(v0.w, v0.w);
            xB[0] = pack2(v1.x, v1.x); xB[1] = pack2(v1.y, v1.y);
            xB[2] = pack2(v1.z, v1.z); xB[3] = pack2(v1.w, v1.w);
            const ull* wbase = sw_em + (ci * 4 + kh) * 48;
            #pragma unroll
            for (int kw = 0; kw < 4; kw++) {
                const ull* wrow = wbase + kw * 12;
                #pragma unroll
                for (int c2 = 0; c2 < 6; c2++) {
                    const ulonglong2 w = *(const ulonglong2*)(wrow + 2 * c2);
                    acc0[2 * c2]     = fma2(xA[kw], w.x, acc0[2 * c2]);
                    acc0[2 * c2 + 1] = fma2(xA[kw], w.y, acc0[2 * c2 + 1]);
                    acc1[2 * c2]     = fma2(xB[kw], w.x, acc1[2 * c2]);
                    acc1[2 * c2 + 1] = fma2(xB[kw], w.y, acc1[2 * c2 + 1]);
                }
            }
        }
    }

    ull pp[CM];
    #pragma unroll
    for (int cp = 0; cp < 12; cp++) {
        const ull a = lrelu2(acc0[cp]);
        const ull bq = lrelu2(acc1[cp]);
        float a0, a1, b0, b1;
        unpack2(a, a0, a1); unpack2(bq, b0, b1);
        pp[2 * cp]     = pack2(a0, b0);
        pp[2 * cp + 1] = pack2(a1, b1);
    }
    rc_epilogue(sw_rc, sb_rc, pp, g_fl, b, hh, t, WL);
}

// ---------------- RIGHT branch: Winograd F(2,4) along width ----------------
// pixels (2t, 2t+1) use input cols d0..d4 = cols 2t-1 .. 2t+3 (pad pl=1, pr=2).
// u = P^T d:  u0 = d0 - d1/2 - d2 + d3/2
//             u1 = d1 + (d2 - d3)/2
//             u2 = (3*d2 - 2*d1 - d3)/6
//             u3 = (d3 - d1)/6
//             u4 = 2*(d1 - d3) - d2 + d4
// M[j] += u_j * W_j  (accumulated over ci,kh);  y0 = M0+M1+M2+M3,  y1 = M1-M2+2*M3+M4.
__device__ __forceinline__ void conv_body_right(const float* __restrict__ in, const ull* sm, int g)
{
    const ull* sw_wg = sm;
    const ull* sw_rc = sm + SM_WG + SM_EM;
    const ull* sb_em = sw_rc + SM_RC;
    const ull* sb_rc = sb_em + 12;

    const int t  = g % 640;
    const int hh = (g / 640) % HO;
    const int b  = g / (640 * HO);

    ull M[5][12];
    #pragma unroll
    for (int j = 0; j < 5; j++)
        #pragma unroll
        for (int cp = 0; cp < 12; cp++) M[j][cp] = 0ULL;

    const float* inb = in + (size_t)b * CIN * HIN * WIN;

    #pragma unroll 1
    for (int ci = 0; ci < CIN; ci++) {
        #pragma unroll
        for (int kh = 0; kh < 4; kh++) {
            const float* row = inb + (size_t)(ci * HIN + 4 * hh + kh) * WIN;
            const float2 vb = *(const float2*)(row + 2 * t);
            float2 va = make_float2(0.f, 0.f);
            float2 vc = make_float2(0.f, 0.f);
            if (t > 0)   va = *(const float2*)(row + 2 * t - 2);
            if (t < 639) vc = *(const float2*)(row + 2 * t + 2);
            const float d0 = va.y, d1 = vb.x, d2 = vb.y, d3 = vc.x, d4 = vc.y;

            const float u0 = (d0 - d2) + 0.5f * (d3 - d1);
            const float u1 = d1 + 0.5f * (d2 - d3);
            const float u2 = (3.f * d2 - 2.f * d1 - d3) * (1.f / 6.f);
            const float u3 = (d3 - d1) * (1.f / 6.f);
            const float u4 = 2.f * (d1 - d3) - d2 + d4;

            ull U[5];
            U[0] = pack2(u0, u0); U[1] = pack2(u1, u1); U[2] = pack2(u2, u2);
            U[3] = pack2(u3, u3); U[4] = pack2(u4, u4);

            const ull* wbase = sw_wg + (ci * 4 + kh) * 60;
            #pragma unroll
            for (int j = 0; j < 5; j++) {
                const ull* wrow = wbase + j * 12;
                #pragma unroll
                for (int c2 = 0; c2 < 6; c2++) {
                    const ulonglong2 w = *(const ulonglong2*)(wrow + 2 * c2);
                    M[j][2 * c2]     = fma2(U[j], w.x, M[j][2 * c2]);
                    M[j][2 * c2 + 1] = fma2(U[j], w.y, M[j][2 * c2 + 1]);
                }
            }
        }
    }

    // inverse transform + bias + leaky, repack to pixel-pairs
    const ull TWO2 = pack2(2.f, 2.f);
    ull pp[CM];
    #pragma unroll
    for (int cp = 0; cp < 12; cp++) {
        ull y0 = add2(add2(M[0][cp], M[1][cp]), add2(M[2][cp], M[3][cp]));
        ull y1 = add2(add2(M[1][cp], neg2(M[2][cp])), fma2(M[3][cp], TWO2, M[4][cp]));
        y0 = lrelu2(add2(y0, sb_em[cp]));
        y1 = lrelu2(add2(y1, sb_em[cp]));
        float a0, a1, b0, b1;
        unpack2(y0, a0, a1); unpack2(y1, b0, b1);
        pp[2 * cp]     = pack2(a0, b0);
        pp[2 * cp + 1] = pack2(a1, b1);
    }
    rc_epilogue(sw_rc, sb_rc, pp, g_fr, b, hh, t, WR);
}

// launch_bounds(128, 2): 256-reg budget per thread. The Winograd body keeps
// ~150 regs live (M[5][12] accumulators); a 3-blocks/SM cap (170 regs) makes
// ptxas spill accumulators inside the 64-iter mainloop. 8 warps/SM (2/SMSP)
// still saturate the rt~4 FFMA2 pipe.
__global__ void __launch_bounds__(128, 2) conv_fused_kernel(
    const float* __restrict__ inL, const float* __restrict__ inR,
    const float* __restrict__ wem, const float* __restrict__ bem,
    const float* __restrict__ wrc, const float* __restrict__ brc)
{
    extern __shared__ ull sm[];
    load_weights_smem(sm, wem, bem, wrc, brc, threadIdx.x, 128);
    __syncthreads();
    const int gb = blockIdx.x;
    if (gb < NLEFT_BLK) conv_body_left (inL, sm, gb * 128 + threadIdx.x);
    else                conv_body_right(inR, sm, (gb - NLEFT_BLK) * 128 + threadIdx.x);
}

// ---------------- cost volume + min/argmin + 25->13 1x1 conv + assemble ----------------
#define XT   64
#define FRS  324    // 320 words + pad (multiple of 4)
#define WB_PAD 340  // 13*25 + 13 = 338, padded to even word count (float2 alignment for s_red)

__global__ void __launch_bounds__(256) cost_kernel(
    const float* __restrict__ wtf, const float* __restrict__ btf, float* __restrict__ out)
{
    extern __shared__ float s[];
    float*  s_fr  = s;                             // [CM][FRS]
    float*  s_fl  = s + CM * FRS;                  // [CM][XT]
    float*  s_wtf = s_fl + CM * XT;                // 13*25
    float*  s_btf = s_wtf + 13 * 25;               // 13
    float2* s_red = (float2*)(s_fl + CM * XT + WB_PAD);  // [256], 8B-aligned

    const int tid = threadIdx.x;
    const int xl  = tid & 63;
    const int dg  = tid >> 6;
    const int x0  = blockIdx.x * XT;
    const int h   = blockIdx.y, b = blockIdx.z;
    const int x   = x0 + xl;

    {
        const int G0 = 4 * x0 - 66;
        #pragma unroll 5
        for (int it = 0; it < 15; it++) {     // CM*160 / 256 == 15 exactly
            const int i = tid + it * 256;
            const int c = i / 160, p = i % 160;
            const int g = G0 + 2 * p;
            float2 v = make_float2(0.f, 0.f);
            if (g >= 0 && g < WR)
                v = *(const float2*)(g_fr + (((size_t)b * CM + c) * HO + h) * WR + g);
            s_fr[c * FRS + 2 * p]     = v.x;
            s_fr[c * FRS + 2 * p + 1] = v.y;
        }
        #pragma unroll
        for (int it = 0; it < 2; it++) {
            const int i = tid + it * 256;
            if (i < CM * (XT / 4)) {
                const int c = i / (XT / 4), q = i % (XT / 4);
                *(float4*)(s_fl + c * XT + 4 * q) =
                    *(const float4*)(g_fl + (((size_t)b * CM + c) * HO + h) * WL + x0 + 4 * q);
            }
        }
        #pragma unroll
        for (int it = 0; it < 2; it++) {
            const int i = tid + it * 256;
            if (i < 13 * 25) s_wtf[i] = wtf[i];
        }
        if (tid < 13) s_btf[tid] = btf[tid];
    }
    __syncthreads();

    float acc[16];
    #pragma unroll
    for (int i = 0; i < 16; i++) acc[i] = 0.f;

    if (x >= 16) {
        #pragma unroll 2
        for (int c = 0; c < CM; c++) {
            const float flc = s_fl[c * XT + xl];
            const float4* rp = (const float4*)(s_fr + c * FRS);
            #pragma unroll
            for (int q = 0; q < 4; q++) {
                const int dq = 4 * dg + q;
                const float4 v = rp[xl + 16 - dq];
                acc[4 * q + 0] += fabsf(flc - v.w);
                acc[4 * q + 1] += fabsf(flc - v.z);
                acc[4 * q + 2] += fabsf(flc - v.y);
                acc[4 * q + 3] += fabsf(flc - v.x);
            }
        }
    } else {
        #pragma unroll 2
        for (int c = 0; c < CM; c++) {
            const float flc = s_fl[c * XT + xl];
            const float* rp = s_fr + c * FRS + 66;
            #pragma unroll
            for (int i = 0; i < 16; i++) {
                int d = 16 * dg + i;
                int idx = 4 * x + 1 - d;
                if (idx < 0) idx = 0;
                acc[i] += fabsf(flc - rp[idx]);
            }
        }
    }

    float* cv = out + (size_t)NB * 16 * HO * WL;
    #pragma unroll
    for (int i = 0; i < 16; i++) {
        const int d = 16 * dg + i;
        cv[(((size_t)b * DMAX + d) * HO + h) * WL + x] = acc[i];
    }

    float best = acc[0]; int bi = 16 * dg;
    #pragma unroll
    for (int i = 1; i < 16; i++)
        if (acc[i] < best) { best = acc[i]; bi = 16 * dg + i; }
    s_red[tid] = make_float2(best, (float)bi);
    __syncthreads();

    if (tid < XT) {
        float2 r = s_red[tid];
        #pragma unroll
        for (int g2 = 1; g2 < 4; g2++) {
            const float2 o = s_red[g2 * 64 + tid];
            if (o.x < r.x) r = o;
        }

        float o13[13];
        #pragma unroll
        for (int o = 0; o < 13; o++) o13[o] = s_btf[o] + s_wtf[o * 25] * r.x;
        #pragma unroll 2
        for (int c = 0; c < CM; c++) {
            const float v = s_fl[c * XT + tid];
            #pragma unroll
            for (int o = 0; o < 13; o++) o13[o] += s_wtf[o * 25 + 1 + c] * v;
        }

        out[(((size_t)b * 16 + 0) * HO + h) * WL + x0 + tid] = r.y;
        out[(((size_t)b * 16 + 1) * HO + h) * WL + x0 + tid] = 0.f;
        out[(((size_t)b * 16 + 2) * HO + h) * WL + x0 + tid] = 0.f;
        #pragma unroll
        for (int o = 0; o < 13; o++) {
            float v = o13[o];
            v = v > 0.f ? v : 0.2f * v;
            out[(((size_t)b * 16 + 3 + o) * HO + h) * WL + x0 + tid] = v;
        }
    }
}

extern "C" void kernel_launch(void* const* d_in, const int* in_sizes, int n_in,
                              void* d_out, int out_size)
{
    const float* fl  = (const float*)d_in[0];
    const float* fr  = (const float*)d_in[1];
    // d_in[2] = max_disp (int32 scalar, fixed 64)
    const float* wem = (const float*)d_in[3];
    const float* bem = (const float*)d_in[4];
    const float* wrc = (const float*)d_in[5];
    const float* brc = (const float*)d_in[6];
    const float* wtf = (const float*)d_in[7];
    const float* btf = (const float*)d_in[8];
    float* out = (float*)d_out;

    const size_t smw = (size_t)SMW_ULL * sizeof(ull);   // ~60 KB
    const size_t sm2 = (size_t)(CM * FRS + CM * XT + WB_PAD) * sizeof(float)
                     + 256 * sizeof(float2);

    cudaFuncSetAttribute(conv_fused_kernel, cudaFuncAttributeMaxDynamicSharedMemorySize, (int)smw);
    cudaFuncSetAttribute(cost_kernel,       cudaFuncAttributeMaxDynamicSharedMemorySize, (int)sm2);

    conv_fused_kernel<<<NLEFT_BLK + NRIGHT_BLK, 128, smw>>>(fl, fr, wem, bem, wrc, brc);
    cost_kernel      <<<dim3(WL / XT, HO, NB), 256, sm2>>>(wtf, btf, out);
}

// round 15
// speedup vs baseline: 1.3919x; 1.3919x over previous
#include <cuda_runtime.h>

#define NB   2
#define CIN  16
#define CM   24
#define HIN  384
#define WIN  1280
#define HO   96
#define WL   320
#define WR   1280
#define DMAX 64

// scratch (device globals: no allocation allowed)
__device__ float g_fl[(size_t)NB*CM*HO*WL];
__device__ float g_fr[(size_t)NB*CM*HO*WR];

typedef unsigned long long ull;

__device__ __forceinline__ ull pack2(float lo, float hi) {
    ull r; asm("mov.b64 %0,{%1,%2};" : "=l"(r) : "f"(lo), "f"(hi)); return r;
}
__device__ __forceinline__ void unpack2(ull v, float& lo, float& hi) {
    asm("mov.b64 {%0,%1},%2;" : "=f"(lo), "=f"(hi) : "l"(v));
}
__device__ __forceinline__ ull fma2(ull a, ull b, ull c) {
    ull d; asm("fma.rn.f32x2 %0,%1,%2,%3;" : "=l"(d) : "l"(a), "l"(b), "l"(c)); return d;
}
__device__ __forceinline__ ull lrelu2(ull v) {
    float lo, hi; unpack2(v, lo, hi);
    lo = lo > 0.f ? lo : 0.2f * lo;
    hi = hi > 0.f ? hi : 0.2f * hi;
    return pack2(lo, hi);
}

// conv smem layout (ull units) — direct form (proven R11):
//   em: s[((ci*4+kh)*4+kw)*12 + cp] = ( wem[2cp][ci][kh][kw], wem[2cp+1][ci][kh][kw] )
//   rc: s2[co*CM + c] = ( wrc[co][c], wrc[co][c] )
#define SM_EM (CIN*16*12)      // 3072 ull
#define SM_RC (CM*CM)          // 576 ull
#define SMW_ULL (SM_EM + SM_RC + 12 + CM)

#define NLEFT_BLK 240          // 2*96*160 / 128   (2 px/thread)
#define NRIGHT_BLK 960         // 2*96*640 / 128

__device__ __forceinline__ void load_weights_smem(ull* sm, const float* wem, const float* bem,
                                                  const float* wrc, const float* brc, int tid, int nthr) {
    ull* sw_em = sm;
    ull* sw_rc = sm + SM_EM;
    ull* sb_em = sw_rc + SM_RC;
    ull* sb_rc = sb_em + 12;
    for (int i = tid; i < SM_EM; i += nthr) {
        const int cp = i % 12;
        const int kw = (i / 12) & 3;
        const int r2 = i / 48;           // ci*4 + kh
        const int kh = r2 & 3, ci = r2 >> 2;
        const float w0 = wem[(((2 * cp    ) * CIN + ci) * 4 + kh) * 4 + kw];
        const float w1 = wem[(((2 * cp + 1) * CIN + ci) * 4 + kh) * 4 + kw];
        sw_em[i] = pack2(w0, w1);
    }
    for (int i = tid; i < SM_RC; i += nthr) { float w = wrc[i]; sw_rc[i] = pack2(w, w); }
    if (tid < 12) sb_em[tid] = pack2(bem[2 * tid], bem[2 * tid + 1]);
    if (tid < CM) { float v = brc[tid]; sb_rc[tid] = pack2(v, v); }
}

// acc layout: acc[px][cp] = channels (2cp, 2cp+1) for pixel px (px in 0..1)
template<bool RIGHT>
__device__ __forceinline__ void conv_body(const float* __restrict__ in, const ull* sm, int g)
{
    const ull* sw_em = sm;
    const ull* sw_rc = sm + SM_EM;
    const ull* sb_em = sw_rc + SM_RC;
    const ull* sb_rc = sb_em + 12;

    const int TPR = RIGHT ? 640 : 160;   // pixel-pairs per row
    const int t  = g % TPR;
    const int hh = (g / TPR) % HO;
    const int b  = g / (TPR * HO);

    ull acc0[12], acc1[12];
    #pragma unroll
    for (int cp = 0; cp < 12; cp++) { acc0[cp] = sb_em[cp]; acc1[cp] = sb_em[cp]; }

    const float* inb = in + (size_t)b * CIN * HIN * WIN;

    #pragma unroll 1
    for (int ci = 0; ci < CIN; ci++) {
        #pragma unroll
        for (int kh = 0; kh < 4; kh++) {
            const float* row = inb + (size_t)(ci * HIN + 4 * hh + kh) * WIN;
            ull xA[4], xB[4];   // duplicated pixel values per kw: xA = px0, xB = px1
            if (RIGHT) {
                // pixels 2t, 2t+1; input cols 2t-1 .. 2t+3 (pad: pl=1, pr=2)
                const float2 vb = *(const float2*)(row + 2 * t);
                float2 va = make_float2(0.f, 0.f);
                float2 vc = make_float2(0.f, 0.f);
                if (t > 0)   va = *(const float2*)(row + 2 * t - 2);
                if (t < 639) vc = *(const float2*)(row + 2 * t + 2);
                const float r0 = va.y, r1 = vb.x, r2 = vb.y, r3 = vc.x, r4 = vc.y;
                xA[0] = pack2(r0, r0); xA[1] = pack2(r1, r1);
                xA[2] = pack2(r2, r2); xA[3] = pack2(r3, r3);
                xB[0] = xA[1]; xB[1] = xA[2]; xB[2] = xA[3];
                xB[3] = pack2(r4, r4);
            } else {
                // pixels 2t, 2t+1; input cols 8t .. 8t+7 (stride 4, no overlap)
                const float4 v0 = *(const float4*)(row + 8 * t);
                const float4 v1 = *(const float4*)(row + 8 * t + 4);
                xA[0] = pack2(v0.x, v0.x); xA[1] = pack2(v0.y, v0.y);
                xA[2] = pack2(v0.z, v0.z); xA[3] = pack2(v0.w, v0.w);
                xB[0] = pack2(v1.x, v1.x); xB[1] = pack2(v1.y, v1.y);
                xB[2] = pack2(v1.z, v1.z); xB[3] = pack2(v1.w, v1.w);
            }
            const ull* wbase = sw_em + (ci * 4 + kh) * 48;
            #pragma unroll
            for (int kw = 0; kw < 4; kw++) {
                const ull* wrow = wbase + kw * 12;
                #pragma unroll
                for (int c2 = 0; c2 < 6; c2++) {
                    const ulonglong2 w = *(const ulonglong2*)(wrow + 2 * c2);
                    acc0[2 * c2]     = fma2(xA[kw], w.x, acc0[2 * c2]);
                    acc0[2 * c2 + 1] = fma2(xA[kw], w.y, acc0[2 * c2 + 1]);
                    acc1[2 * c2]     = fma2(xB[kw], w.x, acc1[2 * c2]);
                    acc1[2 * c2 + 1] = fma2(xB[kw], w.y, acc1[2 * c2 + 1]);
                }
            }
        }
    }

    // leaky relu, then repack in place: channel-pairs -> pixel-pairs
    ull pp[CM];
    #pragma unroll
    for (int cp = 0; cp < 12; cp++) {
        const ull a = lrelu2(acc0[cp]);
        const ull bq = lrelu2(acc1[cp]);
        float a0, a1, b0, b1;
        unpack2(a, a0, a1); unpack2(bq, b0, b1);
        pp[2 * cp]     = pack2(a0, b0);
        pp[2 * cp + 1] = pack2(a1, b1);
    }

    float* gout = RIGHT ? g_fr : g_fl;
    const int W = RIGHT ? WR : WL;

    #pragma unroll 2
    for (int co = 0; co < CM; co++) {
        ull s = sb_rc[co];
        #pragma unroll
        for (int c2 = 0; c2 < CM / 2; c2++) {
            const ulonglong2 w = *(const ulonglong2*)(sw_rc + co * CM + 2 * c2);
            s = fma2(pp[2 * c2], w.x, s);
            s = fma2(pp[2 * c2 + 1], w.y, s);
        }
        s = lrelu2(s);
        float lo, hi; unpack2(s, lo, hi);
        *(float2*)(gout + (((size_t)b * CM + co) * HO + hh) * W + 2 * t) = make_float2(lo, hi);
    }
}

__global__ void __launch_bounds__(128, 5) conv_fused_kernel(
    const float* __restrict__ inL, const float* __restrict__ inR,
    const float* __restrict__ wem, const float* __restrict__ bem,
    const float* __restrict__ wrc, const float* __restrict__ brc)
{
    extern __shared__ ull sm[];
    load_weights_smem(sm, wem, bem, wrc, brc, threadIdx.x, 128);
    __syncthreads();
    const int gb = blockIdx.x;
    if (gb < NLEFT_BLK) conv_body<false>(inL, sm, gb * 128 + threadIdx.x);
    else                conv_body<true >(inR, sm, (gb - NLEFT_BLK) * 128 + threadIdx.x);
}

// ---------------- cost volume + min/argmin + 25->13 1x1 conv + assemble ----------------
// Tiled: block = (b, h, x-tile of 32). 256 threads = 8 disparity groups x 32 x.
// smem fr window: s_fr[c][j] = fr[c][4*x0 - 66 + j], j in [0,196); float4 at word
// index 4k covers fr[4*x0-66+4k .. +3]; float4 idx (xl+16-dq) covers
// fr[4x-4dq-2 .. 4x-4dq+1]  ->  .w = d=4dq, .z = d=4dq+1, .y = +2, .x = +3
#define XT   32
#define FRS  196    // 192 words window + pad (multiple of 4 -> 16B-aligned rows)
#define WB_PAD 340  // 13*25 + 13 = 338, padded to even word count (float2 alignment for s_red)

__global__ void __launch_bounds__(256) cost_kernel(
    const float* __restrict__ wtf, const float* __restrict__ btf, float* __restrict__ out)
{
    extern __shared__ float s[];
    float*  s_fr  = s;                             // [CM][FRS]
    float*  s_fl  = s + CM * FRS;                  // [CM][XT]
    float*  s_wtf = s_fl + CM * XT;                // 13*25
    float*  s_btf = s_wtf + 13 * 25;               // 13
    float2* s_red = (float2*)(s_fl + CM * XT + WB_PAD);  // [256], 8B-aligned (even word offset)

    const int tid = threadIdx.x;
    const int xl  = tid & 31;                 // local x
    const int dg  = tid >> 5;                 // disparity group: d in [8*dg, 8*dg+7]
    const int x0  = blockIdx.x * XT;
    const int h   = blockIdx.y, b = blockIdx.z;
    const int x   = x0 + xl;

    // ---- stage smem ----
    {
        const int G0 = 4 * x0 - 66;           // even -> float2 aligned
        #pragma unroll 5
        for (int it = 0; it < 10; it++) {     // CM*(FRS/2) = 2352 entries, 256/thread-step
            const int i = tid + it * 256;
            if (i < CM * (FRS / 2)) {
                const int c = i / (FRS / 2), p = i % (FRS / 2);
                const int g = G0 + 2 * p;
                float2 v = make_float2(0.f, 0.f);
                if (g >= 0 && g < WR)
                    v = *(const float2*)(g_fr + (((size_t)b * CM + c) * HO + h) * WR + g);
                s_fr[c * FRS + 2 * p]     = v.x;
                s_fr[c * FRS + 2 * p + 1] = v.y;
            }
        }
        // fl: CM*(XT/4) = 192 float4 entries, single pass
        if (tid < CM * (XT / 4)) {
            const int c = tid / (XT / 4), q = tid % (XT / 4);
            *(float4*)(s_fl + c * XT + 4 * q) =
                *(const float4*)(g_fl + (((size_t)b * CM + c) * HO + h) * WL + x0 + 4 * q);
        }
        #pragma unroll
        for (int it = 0; it < 2; it++) {
            const int i = tid + it * 256;
            if (i < 13 * 25) s_wtf[i] = wtf[i];
        }
        if (tid < 13) s_btf[tid] = btf[tid];
    }
    __syncthreads();

    // ---- accumulate 8 disparities per thread ----
    float acc[8];
    #pragma unroll
    for (int i = 0; i < 8; i++) acc[i] = 0.f;

    if (x >= 16) {
        #pragma unroll 2
        for (int c = 0; c < CM; c++) {
            const float flc = s_fl[c * XT + xl];
            const float4* rp = (const float4*)(s_fr + c * FRS);
            #pragma unroll
            for (int q = 0; q < 2; q++) {
                const int dq = 2 * dg + q;
                const float4 v = rp[xl + 16 - dq];
                acc[4 * q + 0] += fabsf(flc - v.w);
                acc[4 * q + 1] += fabsf(flc - v.z);
                acc[4 * q + 2] += fabsf(flc - v.y);
                acc[4 * q + 3] += fabsf(flc - v.x);
            }
        }
    } else {   // only tile 0, x<16: clipped indices
        #pragma unroll 2
        for (int c = 0; c < CM; c++) {
            const float flc = s_fl[c * XT + xl];
            const float* rp = s_fr + c * FRS + 66;   // rp[i] = fr[i] (x0 == 0)
            #pragma unroll
            for (int i = 0; i < 8; i++) {
                int d = 8 * dg + i;
                int idx = 4 * x + 1 - d;
                if (idx < 0) idx = 0;
                acc[i] += fabsf(flc - rp[idx]);
            }
        }
    }

    // ---- write cost volume slice ----
    float* cv = out + (size_t)NB * 16 * HO * WL;
    #pragma unroll
    for (int i = 0; i < 8; i++) {
        const int d = 8 * dg + i;
        cv[(((size_t)b * DMAX + d) * HO + h) * WL + x] = acc[i];
    }

    // ---- per-thread min/argmin (ascending d, strict < = first occurrence) ----
    float best = acc[0]; int bi = 8 * dg;
    #pragma unroll
    for (int i = 1; i < 8; i++)
        if (acc[i] < best) { best = acc[i]; bi = 8 * dg + i; }
    s_red[tid] = make_float2(best, (float)bi);
    __syncthreads();

    // ---- final reduce + 25->13 conv + assemble (32 threads) ----
    if (tid < XT) {
        float2 r = s_red[tid];
        #pragma unroll
        for (int g2 = 1; g2 < 8; g2++) {
            const float2 o = s_red[g2 * 32 + tid];
            if (o.x < r.x) r = o;
        }

        float o13[13];
        #pragma unroll
        for (int o = 0; o < 13; o++) o13[o] = s_btf[o] + s_wtf[o * 25] * r.x;
        #pragma unroll 2
        for (int c = 0; c < CM; c++) {
            const float v = s_fl[c * XT + tid];
            #pragma unroll
            for (int o = 0; o < 13; o++) o13[o] += s_wtf[o * 25 + 1 + c] * v;
        }

        out[(((size_t)b * 16 + 0) * HO + h) * WL + x0 + tid] = r.y;
        out[(((size_t)b * 16 + 1) * HO + h) * WL + x0 + tid] = 0.f;
        out[(((size_t)b * 16 + 2) * HO + h) * WL + x0 + tid] = 0.f;
        #pragma unroll
        for (int o = 0; o < 13; o++) {
            float v = o13[o];
            v = v > 0.f ? v : 0.2f * v;
            out[(((size_t)b * 16 + 3 + o) * HO + h) * WL + x0 + tid] = v;
        }
    }
}

extern "C" void kernel_launch(void* const* d_in, const int* in_sizes, int n_in,
                              void* d_out, int out_size)
{
    const float* fl  = (const float*)d_in[0];
    const float* fr  = (const float*)d_in[1];
    // d_in[2] = max_disp (int32 scalar, fixed 64)
    const float* wem = (const float*)d_in[3];
    const float* bem = (const float*)d_in[4];
    const float* wrc = (const float*)d_in[5];
    const float* brc = (const float*)d_in[6];
    const float* wtf = (const float*)d_in[7];
    const float* btf = (const float*)d_in[8];
    float* out = (float*)d_out;

    const size_t smw = (size_t)SMW_ULL * sizeof(ull);   // ~29.5 KB
    const size_t sm2 = (size_t)(CM * FRS + CM * XT + WB_PAD) * sizeof(float)
                     + 256 * sizeof(float2);            // ~25.3 KB -> 8 blocks/SM (warp cap)

    cudaFuncSetAttribute(conv_fused_kernel, cudaFuncAttributeMaxDynamicSharedMemorySize, (int)smw);
    cudaFuncSetAttribute(cost_kernel,       cudaFuncAttributeMaxDynamicSharedMemorySize, (int)sm2);

    conv_fused_kernel<<<NLEFT_BLK + NRIGHT_BLK, 128, smw>>>(fl, fr, wem, bem, wrc, brc);
    cost_kernel      <<<dim3(WL / XT, HO, NB), 256, sm2>>>(wtf, btf, out);
}